// round 3
// baseline (speedup 1.0000x reference)
#include <cuda_runtime.h>
#include <math.h>
#include <stdint.h>

// Problem constants
#define S_ 512
#define B_ 64
#define E_ 300
#define H_ 256
#define T_ 9

// ---------------- device scratch (no runtime allocation allowed) ----------
__device__ float g_xp[(size_t)2 * 512 * 1024 * 64];   // [dir][t][gate_row 0..1023][b]  (256 MB)
__device__ float g_hT[(size_t)512 * 512 * 64];        // [t][col 0..511][b]; col<256 fwd, >=256 bwd (67 MB)
__device__ float g_emis[(size_t)512 * 64 * 9];        // [t][b][tau]
__device__ float g_llh[64];
__device__ int          g_cnt[64];                    // per-dir barrier counters (padded: idx d*32)
__device__ volatile int g_sense[64];                  // per-dir barrier sense

// ===========================================================================
// K1: fused embedding gather + input projection GEMM (+ bih+bhh bias)
//   grid (t=512, ctile=32) ; ctile<16 -> fwd rows [64*ctile..), else bwd
//   block 256 threads, 64(c) x 64(b) tile, K=300 in 5 chunks of 60
// ===========================================================================
__global__ void __launch_bounds__(256) k_inproj(
    const int*   __restrict__ sent,
    const float* __restrict__ embed,
    const float* __restrict__ wih_f, const float* __restrict__ wih_b,
    const float* __restrict__ bih_f, const float* __restrict__ bhh_f,
    const float* __restrict__ bih_b, const float* __restrict__ bhh_b)
{
    __shared__ float As[64 * 61];   // wih tile [c][k], padded
    __shared__ float Bs[64 * 61];   // embed tile [b][k], padded
    __shared__ int   words[64];

    const int t     = blockIdx.x;
    const int ctile = blockIdx.y;
    const int d     = ctile >> 4;
    const int c0    = (ctile & 15) * 64;
    const int tid   = threadIdx.x;

    const float* wih = d ? wih_b : wih_f;
    const float* bih = d ? bih_b : bih_f;
    const float* bhh = d ? bhh_b : bhh_f;

    if (tid < 64) words[tid] = sent[tid * S_ + t];
    __syncthreads();

    const int ty = tid >> 4;   // 0..15 -> c group
    const int tx = tid & 15;   // 0..15 -> b group
    float acc[4][4] = {};

    for (int k0 = 0; k0 < 300; k0 += 60) {
        for (int idx = tid; idx < 64 * 60; idx += 256) {
            int r = idx / 60, k = idx - r * 60;
            As[r * 61 + k] = wih[(size_t)(c0 + r) * 300 + k0 + k];
            Bs[r * 61 + k] = embed[(size_t)words[r] * 300 + k0 + k];
        }
        __syncthreads();
        #pragma unroll 10
        for (int k = 0; k < 60; k++) {
            float a[4], bb[4];
            #pragma unroll
            for (int i = 0; i < 4; i++) a[i]  = As[(ty * 4 + i) * 61 + k];
            #pragma unroll
            for (int j = 0; j < 4; j++) bb[j] = Bs[(tx * 4 + j) * 61 + k];
            #pragma unroll
            for (int i = 0; i < 4; i++)
                #pragma unroll
                for (int j = 0; j < 4; j++)
                    acc[i][j] += a[i] * bb[j];
        }
        __syncthreads();
    }

    const size_t obase = ((size_t)d * 512 + t) * 65536;  // 1024*64
    #pragma unroll
    for (int i = 0; i < 4; i++) {
        int c = c0 + ty * 4 + i;
        float bias = bih[c] + bhh[c];
        float4 v = make_float4(acc[i][0] + bias, acc[i][1] + bias,
                               acc[i][2] + bias, acc[i][3] + bias);
        *(float4*)&g_xp[obase + (size_t)c * 64 + tx * 4] = v;
    }
}

// ===========================================================================
// K2: persistent bidirectional LSTM recurrence.
//   grid 128 (64 CTAs/dir), block 256. CTA m owns h-cols [4m, 4m+4).
//   thread (hcl = tid/64, b = tid%64) keeps c-state in a register for 512 steps.
//   whh slice (16 rows x 256) pinned in smem; h read directly from global
//   (fresh address every step -> no L1 staleness); one L2 sense-reversal
//   barrier per dir per step (512 flips/launch = even -> replay-safe).
// ===========================================================================
__global__ void __launch_bounds__(256, 1) k_rec(
    const float* __restrict__ whh_f, const float* __restrict__ whh_b)
{
    __shared__ __align__(16) float whh_s[16 * 256];   // [gate*4 + hcl][j]

    const int bx  = blockIdx.x;
    const int d   = bx >> 6;          // direction
    const int m   = bx & 63;
    const int hc0 = m * 4;
    const int tid = threadIdx.x;
    const int hcl = tid >> 6;         // 0..3 local h-col
    const int b   = tid & 63;
    const int colbase = d * 256;
    const float* whh = d ? whh_b : whh_f;

    for (int idx = tid; idx < 4096; idx += 256) {
        int r = idx >> 8, j = idx & 255;
        int g = r >> 2, hl = r & 3;
        whh_s[idx] = whh[(size_t)(g * 256 + hc0 + hl) * 256 + j];
    }
    __syncthreads();

    const float4* w4 = (const float4*)whh_s;
    const int wi = (0 * 4 + hcl) * 64;
    const int wf = (1 * 4 + hcl) * 64;
    const int wg = (2 * 4 + hcl) * 64;
    const int wo = (3 * 4 + hcl) * 64;

    float cstate = 0.f;

    for (int t = 0; t < 512; t++) {
        const int tt = d ? (511 - t) : t;

        const size_t xpb = ((size_t)d * 512 + tt) * 65536;
        const float xi = g_xp[xpb + (size_t)(0 * 256 + hc0 + hcl) * 64 + b];
        const float xf = g_xp[xpb + (size_t)(1 * 256 + hc0 + hcl) * 64 + b];
        const float xg = g_xp[xpb + (size_t)(2 * 256 + hc0 + hcl) * 64 + b];
        const float xo = g_xp[xpb + (size_t)(3 * 256 + hc0 + hcl) * 64 + b];

        float ai = 0.f, af = 0.f, ag = 0.f, ao = 0.f;

        if (t > 0) {
            const int hp = d ? (tt + 1) : (tt - 1);
            const float* __restrict__ hsrc =
                &g_hT[(size_t)hp * 32768 + (size_t)colbase * 64 + b];
            #pragma unroll 8
            for (int jq = 0; jq < 64; jq++) {
                float h0 = hsrc[(jq * 4 + 0) * 64];
                float h1 = hsrc[(jq * 4 + 1) * 64];
                float h2 = hsrc[(jq * 4 + 2) * 64];
                float h3 = hsrc[(jq * 4 + 3) * 64];
                float4 vi = w4[wi + jq];
                float4 vf = w4[wf + jq];
                float4 vg = w4[wg + jq];
                float4 vo = w4[wo + jq];
                ai += vi.x * h0; ai += vi.y * h1; ai += vi.z * h2; ai += vi.w * h3;
                af += vf.x * h0; af += vf.y * h1; af += vf.z * h2; af += vf.w * h3;
                ag += vg.x * h0; ag += vg.y * h1; ag += vg.z * h2; ag += vg.w * h3;
                ao += vo.x * h0; ao += vo.y * h1; ao += vo.z * h2; ao += vo.w * h3;
            }
        }
        ai += xi; af += xf; ag += xg; ao += xo;

        const float si = 1.f / (1.f + expf(-ai));
        const float sf = 1.f / (1.f + expf(-af));
        const float so = 1.f / (1.f + expf(-ao));
        cstate = sf * cstate + si * tanhf(ag);
        const float hval = so * tanhf(cstate);

        g_hT[(size_t)tt * 32768 + (size_t)(colbase + hc0 + hcl) * 64 + b] = hval;

        // inter-CTA barrier (per direction)
        __threadfence();
        __syncthreads();
        if (tid == 0) {
            const int idx = d * 32;
            const int phase = (t & 1) ^ 1;
            int ticket = atomicAdd(&g_cnt[idx], 1);
            if (ticket == 63) {
                atomicExch(&g_cnt[idx], 0);
                __threadfence();
                atomicExch((int*)&g_sense[idx], phase);
            } else {
                while (g_sense[idx] != phase) { __nanosleep(64); }
            }
        }
        __syncthreads();
    }
}

// ===========================================================================
// K3: emissions GEMM  emis[t][b][tau] = sum_c hT[t][c][b] * w_out[tau][c] + b_out
//   grid 512 (t), block 256. 4 K-segments of 128 reduced in smem.
// ===========================================================================
__global__ void __launch_bounds__(256) k_emis(
    const float* __restrict__ w_out, const float* __restrict__ b_out)
{
    __shared__ float w_s[9 * 512];
    __shared__ float red[4][64][10];

    const int t = blockIdx.x, tid = threadIdx.x;
    for (int i = tid; i < 9 * 512; i += 256) w_s[i] = w_out[i];
    __syncthreads();

    const int b = tid & 63, seg = tid >> 6;
    float acc[9] = {};
    const float* hbase = &g_hT[(size_t)t * 32768];
    const int cbeg = seg * 128;
    for (int c = cbeg; c < cbeg + 128; c++) {
        float hv = hbase[(size_t)c * 64 + b];
        #pragma unroll
        for (int tau = 0; tau < 9; tau++) acc[tau] += hv * w_s[tau * 512 + c];
    }
    #pragma unroll
    for (int tau = 0; tau < 9; tau++) red[seg][b][tau] = acc[tau];
    __syncthreads();
    if (seg == 0) {
        #pragma unroll
        for (int tau = 0; tau < 9; tau++) {
            float v = red[0][b][tau] + red[1][b][tau] + red[2][b][tau] +
                      red[3][b][tau] + b_out[tau];
            g_emis[(size_t)t * 576 + b * 9 + tau] = v;
        }
    }
}

// ===========================================================================
// K4: CRF gold score + forward algorithm (logZ). grid 64 (b), 1 warp each.
// ===========================================================================
__global__ void k_crf(
    const int*   __restrict__ tags, const int* __restrict__ mask,
    const float* __restrict__ start_trans, const float* __restrict__ end_trans,
    const float* __restrict__ trans)
{
    const int b = blockIdx.x, lane = threadIdx.x;

    // ---- gold score (lane-strided over t) ----
    float sc = 0.f; int cnt = 0;
    for (int t = lane; t < 512; t += 32) {
        int mk = mask[b * 512 + t];
        cnt += mk;
        if (t >= 1 && mk) {
            int tp = tags[b * 512 + t - 1];
            int tc = tags[b * 512 + t];
            sc += trans[tp * 9 + tc] + g_emis[(size_t)t * 576 + b * 9 + tc];
        }
    }
    #pragma unroll
    for (int o = 16; o > 0; o >>= 1) {
        sc  += __shfl_down_sync(0xffffffffu, sc, o);
        cnt += __shfl_down_sync(0xffffffffu, cnt, o);
    }
    int len = __shfl_sync(0xffffffffu, cnt, 0);
    float score = 0.f;
    if (lane == 0) {
        int t0 = tags[b * 512];
        score = sc + start_trans[t0] + g_emis[b * 9 + t0];
        int tl = tags[b * 512 + len - 1];
        score += end_trans[tl];
    }

    // ---- forward algorithm on lanes 0..8 ----
    float logZ = 0.f;
    if (lane < 9) {
        const int j = lane;
        float tr[9];
        #pragma unroll
        for (int i = 0; i < 9; i++) tr[i] = trans[i * 9 + j];
        float alpha = start_trans[j] + g_emis[b * 9 + j];
        for (int t = 1; t < 512; t++) {
            if (!mask[b * 512 + t]) break;   // mask is a contiguous prefix
            float em = g_emis[(size_t)t * 576 + b * 9 + j];
            float v[9];
            #pragma unroll
            for (int i = 0; i < 9; i++)
                v[i] = __shfl_sync(0x1ffu, alpha, i) + tr[i];
            float mx = v[0];
            #pragma unroll
            for (int i = 1; i < 9; i++) mx = fmaxf(mx, v[i]);
            float s = 0.f;
            #pragma unroll
            for (int i = 0; i < 9; i++) s += expf(v[i] - mx);
            alpha = mx + logf(s) + em;
        }
        float z = alpha + end_trans[j];
        float zz[9];
        #pragma unroll
        for (int i = 0; i < 9; i++) zz[i] = __shfl_sync(0x1ffu, z, i);
        float mx = zz[0];
        #pragma unroll
        for (int i = 1; i < 9; i++) mx = fmaxf(mx, zz[i]);
        float s = 0.f;
        #pragma unroll
        for (int i = 0; i < 9; i++) s += expf(zz[i] - mx);
        logZ = mx + logf(s);
    }
    if (lane == 0) g_llh[b] = score - logZ;
}

// ===========================================================================
// K5: final deterministic reduction  out = -mean(llh)
// ===========================================================================
__global__ void k_final(float* __restrict__ out)
{
    __shared__ float s[64];
    const int tid = threadIdx.x;
    s[tid] = g_llh[tid];
    __syncthreads();
    if (tid == 0) {
        float acc = 0.f;
        for (int i = 0; i < 64; i++) acc += s[i];
        out[0] = -acc / 64.f;
    }
}

// ===========================================================================
extern "C" void kernel_launch(void* const* d_in, const int* in_sizes, int n_in,
                              void* d_out, int out_size)
{
    // Two plausible input orderings: setup_inputs dict order (mask last) or
    // reference signature order (mask at index 2). Distinguish via embed size.
    const bool dictOrder = (in_sizes[2] == 15000000);
    const int ie = dictOrder ? 2 : 3;
    const int im = dictOrder ? 16 : 2;

    const int*   sent    = (const int*)  d_in[0];
    const int*   tags    = (const int*)  d_in[1];
    const float* embed   = (const float*)d_in[ie + 0];
    const float* wih_f   = (const float*)d_in[ie + 1];
    const float* whh_f   = (const float*)d_in[ie + 2];
    const float* bih_f   = (const float*)d_in[ie + 3];
    const float* bhh_f   = (const float*)d_in[ie + 4];
    const float* wih_b   = (const float*)d_in[ie + 5];
    const float* whh_b   = (const float*)d_in[ie + 6];
    const float* bih_b   = (const float*)d_in[ie + 7];
    const float* bhh_b   = (const float*)d_in[ie + 8];
    const float* w_out   = (const float*)d_in[ie + 9];
    const float* b_out   = (const float*)d_in[ie + 10];
    const float* s_tr    = (const float*)d_in[ie + 11];
    const float* e_tr    = (const float*)d_in[ie + 12];
    const float* trans   = (const float*)d_in[ie + 13];
    const int*   mask    = (const int*)  d_in[im];
    float*       out     = (float*)d_out;

    dim3 g1(512, 32);
    k_inproj<<<g1, 256>>>(sent, embed, wih_f, wih_b, bih_f, bhh_f, bih_b, bhh_b);
    k_rec<<<128, 256>>>(whh_f, whh_b);
    k_emis<<<512, 256>>>(w_out, b_out);
    k_crf<<<64, 32>>>(tags, mask, s_tr, e_tr, trans);
    k_final<<<1, 64>>>(out);
}

// round 4
// speedup vs baseline: 1.1350x; 1.1350x over previous
#include <cuda_runtime.h>
#include <math.h>
#include <stdint.h>

// ---------------- device scratch ----------------
__device__ float g_xp[(size_t)2 * 512 * 1024 * 64];   // [dir][t][gate_row 0..1023][b]
__device__ float g_hT[(size_t)512 * 512 * 64];        // [t][col 0..511][b]; col<256 fwd
__device__ float g_emis[(size_t)512 * 64 * 9];        // [t][b][tau]
__device__ float g_llh[64];
__device__ int          g_cnt[64];                    // per-dir barrier counters (idx d*32)
__device__ volatile int g_sense[64];                  // per-dir barrier sense

// ---------------- packed f32x2 helpers (Blackwell FFMA2) ----------------
__device__ __forceinline__ unsigned long long ffma2(unsigned long long a,
                                                    unsigned long long b,
                                                    unsigned long long c) {
    unsigned long long d;
    asm("fma.rn.f32x2 %0, %1, %2, %3;" : "=l"(d) : "l"(a), "l"(b), "l"(c));
    return d;
}
__device__ __forceinline__ unsigned long long pack2(float lo, float hi) {
    unsigned long long d;
    asm("mov.b64 %0, {%1, %2};" : "=l"(d) : "f"(lo), "f"(hi));
    return d;
}
__device__ __forceinline__ float hsum2(unsigned long long v) {
    float lo, hi;
    asm("mov.b64 {%0, %1}, %2;" : "=f"(lo), "=f"(hi) : "l"(v));
    return lo + hi;
}

// ===========================================================================
// K1: fused embedding gather + input projection GEMM (+ bih+bhh bias)
//   grid (t=512, ctile=32); 64(c) x 64(b) tile, K=300 in 5 chunks of 60.
//   k-pair FFMA2: acc pairs accumulate (even-k, odd-k) partial sums.
//   Microtile mapping c = ty + 16*i, b = tx + 16*j keeps LDS.64 banks clean.
// ===========================================================================
__global__ void __launch_bounds__(256) k_inproj(
    const int*   __restrict__ sent,
    const float* __restrict__ embed,
    const float* __restrict__ wih_f, const float* __restrict__ wih_b,
    const float* __restrict__ bih_f, const float* __restrict__ bhh_f,
    const float* __restrict__ bih_b, const float* __restrict__ bhh_b)
{
    __shared__ float As[64 * 66];   // wih tile [c][k], pad 66 (even, 2-way banks)
    __shared__ float Bs[64 * 66];   // embed tile [b][k]
    __shared__ int   words[64];

    const int t     = blockIdx.x;
    const int ctile = blockIdx.y;
    const int d     = ctile >> 4;
    const int c0    = (ctile & 15) * 64;
    const int tid   = threadIdx.x;

    const float* __restrict__ wih = d ? wih_b : wih_f;
    const float* __restrict__ bih = d ? bih_b : bih_f;
    const float* __restrict__ bhh = d ? bhh_b : bhh_f;

    if (tid < 64) words[tid] = sent[tid * 512 + t];
    __syncthreads();

    const int ty = tid >> 4;   // 0..15
    const int tx = tid & 15;   // 0..15

    unsigned long long acc[4][4];
    #pragma unroll
    for (int i = 0; i < 4; i++)
        #pragma unroll
        for (int j = 0; j < 4; j++) acc[i][j] = 0ull;

    for (int k0 = 0; k0 < 300; k0 += 60) {
        for (int idx = tid; idx < 64 * 60; idx += 256) {
            int r = idx / 60, k = idx - r * 60;
            As[r * 66 + k] = wih[(size_t)(c0 + r) * 300 + k0 + k];
            Bs[r * 66 + k] = embed[(size_t)words[r] * 300 + k0 + k];
        }
        __syncthreads();
        #pragma unroll 6
        for (int kk = 0; kk < 30; kk++) {
            const int k = 2 * kk;
            unsigned long long a2[4], b2[4];
            #pragma unroll
            for (int i = 0; i < 4; i++)
                a2[i] = *(const unsigned long long*)&As[(ty + 16 * i) * 66 + k];
            #pragma unroll
            for (int j = 0; j < 4; j++)
                b2[j] = *(const unsigned long long*)&Bs[(tx + 16 * j) * 66 + k];
            #pragma unroll
            for (int i = 0; i < 4; i++)
                #pragma unroll
                for (int j = 0; j < 4; j++)
                    acc[i][j] = ffma2(a2[i], b2[j], acc[i][j]);
        }
        __syncthreads();
    }

    const size_t obase = ((size_t)d * 512 + t) * 65536;  // 1024*64
    #pragma unroll
    for (int i = 0; i < 4; i++) {
        int c = c0 + ty + 16 * i;
        float bias = bih[c] + bhh[c];
        #pragma unroll
        for (int j = 0; j < 4; j++)
            g_xp[obase + (size_t)c * 64 + tx + 16 * j] = hsum2(acc[i][j]) + bias;
    }
}

// ===========================================================================
// K2: persistent bidirectional LSTM recurrence.
//   grid 128 (64 CTAs/dir), 256 thr. CTA m owns h-cols [4m, 4m+4).
//   Per step: stage h_prev[256][64] (64KB) into smem cooperatively, then
//   j-pair FFMA2 GEMM with interleaved gate-pair weights (broadcast LDS.128).
//   One L2 sense-reversal barrier per dir per step (512 flips = replay-safe).
//   Dynamic smem: wint 16KB + hstage 64KB = 80KB.
// ===========================================================================
__global__ void __launch_bounds__(256, 1) k_rec(
    const float* __restrict__ whh_f, const float* __restrict__ whh_b)
{
    extern __shared__ float dsm[];
    float* wint   = dsm;            // 4096 floats: [hcl][jp][ wi0,wi1,wf0,wf1,wg0,wg1,wo0,wo1 ]
    float* hstage = dsm + 4096;     // 16384 floats: [j][b]

    const int bx  = blockIdx.x;
    const int d   = bx >> 6;
    const int m   = bx & 63;
    const int hc0 = m * 4;
    const int tid = threadIdx.x;
    const int hcl = tid >> 6;       // 0..3
    const int b   = tid & 63;
    const int colbase = d * 256;
    const float* __restrict__ whh = d ? whh_b : whh_f;

    // interleaved gate-pair weight layout
    for (int idx = tid; idx < 4096; idx += 256) {
        int r  = idx >> 3, s = idx & 7;
        int hl = r >> 7,  jp = r & 127;
        int g  = s >> 1,  kb = s & 1;
        wint[idx] = whh[(size_t)(g * 256 + hc0 + hl) * 256 + 2 * jp + kb];
    }
    __syncthreads();

    const ulonglong2* __restrict__ wp = (const ulonglong2*)(wint + hcl * 1024);

    float cstate = 0.f;

    for (int t = 0; t < 512; t++) {
        const int tt = d ? (511 - t) : t;

        const size_t xpb = ((size_t)d * 512 + tt) * 65536;
        const float xi = g_xp[xpb + (size_t)(hc0 + hcl) * 64 + b];
        const float xf = g_xp[xpb + (size_t)(256 + hc0 + hcl) * 64 + b];
        const float xg = g_xp[xpb + (size_t)(512 + hc0 + hcl) * 64 + b];
        const float xo = g_xp[xpb + (size_t)(768 + hc0 + hcl) * 64 + b];

        float ai, af, ag, ao;

        if (t > 0) {
            const int hp = d ? (tt + 1) : (tt - 1);
            // cooperative stage: 64KB, fully coalesced, max MLP
            const float4* __restrict__ src =
                (const float4*)&g_hT[(size_t)hp * 32768 + (size_t)colbase * 64];
            float4 stg[16];
            #pragma unroll
            for (int i = 0; i < 16; i++) stg[i] = src[i * 256 + tid];
            float4* dst = (float4*)hstage;
            #pragma unroll
            for (int i = 0; i < 16; i++) dst[i * 256 + tid] = stg[i];
            __syncthreads();

            unsigned long long ai2 = 0, af2 = 0, ag2 = 0, ao2 = 0;
            #pragma unroll 8
            for (int jp = 0; jp < 128; jp++) {
                float h0 = hstage[jp * 128 + b];
                float h1 = hstage[jp * 128 + 64 + b];
                unsigned long long hh = pack2(h0, h1);
                ulonglong2 w01 = wp[2 * jp];
                ulonglong2 w23 = wp[2 * jp + 1];
                ai2 = ffma2(w01.x, hh, ai2);
                af2 = ffma2(w01.y, hh, af2);
                ag2 = ffma2(w23.x, hh, ag2);
                ao2 = ffma2(w23.y, hh, ao2);
            }
            ai = hsum2(ai2) + xi; af = hsum2(af2) + xf;
            ag = hsum2(ag2) + xg; ao = hsum2(ao2) + xo;
        } else {
            ai = xi; af = xf; ag = xg; ao = xo;
        }

        const float si = 1.f / (1.f + __expf(-ai));
        const float sf = 1.f / (1.f + __expf(-af));
        const float so = 1.f / (1.f + __expf(-ao));
        cstate = sf * cstate + si * tanhf(ag);
        const float hval = so * tanhf(cstate);

        g_hT[(size_t)tt * 32768 + (size_t)(colbase + hc0 + hcl) * 64 + b] = hval;

        __threadfence();
        __syncthreads();
        if (tid == 0) {
            const int idx = d * 32;
            const int phase = (t & 1) ^ 1;
            int ticket = atomicAdd(&g_cnt[idx], 1);
            if (ticket == 63) {
                g_cnt[idx] = 0;
                __threadfence();
                atomicExch((int*)&g_sense[idx], phase);
            } else {
                while (g_sense[idx] != phase) { __nanosleep(32); }
            }
        }
        __syncthreads();
    }
}

// ===========================================================================
// K3: emissions GEMM  emis[t][b][tau] = sum_c hT[t][c][b]*w_out[tau][c]+b_out
// ===========================================================================
__global__ void __launch_bounds__(256) k_emis(
    const float* __restrict__ w_out, const float* __restrict__ b_out)
{
    __shared__ float w_s[9 * 512];
    __shared__ float red[4][64][10];

    const int t = blockIdx.x, tid = threadIdx.x;
    for (int i = tid; i < 9 * 512; i += 256) w_s[i] = w_out[i];
    __syncthreads();

    const int b = tid & 63, seg = tid >> 6;
    float acc[9] = {};
    const float* hbase = &g_hT[(size_t)t * 32768];
    const int cbeg = seg * 128;
    for (int c = cbeg; c < cbeg + 128; c++) {
        float hv = hbase[(size_t)c * 64 + b];
        #pragma unroll
        for (int tau = 0; tau < 9; tau++) acc[tau] += hv * w_s[tau * 512 + c];
    }
    #pragma unroll
    for (int tau = 0; tau < 9; tau++) red[seg][b][tau] = acc[tau];
    __syncthreads();
    if (seg == 0) {
        #pragma unroll
        for (int tau = 0; tau < 9; tau++) {
            float v = red[0][b][tau] + red[1][b][tau] + red[2][b][tau] +
                      red[3][b][tau] + b_out[tau];
            g_emis[(size_t)t * 576 + b * 9 + tau] = v;
        }
    }
}

// ===========================================================================
// K4: CRF gold score + forward algorithm (logZ). grid 64 (b), 1 warp each.
//     Fast-math exp/log + one-step-ahead prefetch of em/mask.
// ===========================================================================
__global__ void k_crf(
    const int*   __restrict__ tags, const int* __restrict__ mask,
    const float* __restrict__ start_trans, const float* __restrict__ end_trans,
    const float* __restrict__ trans)
{
    const int b = blockIdx.x, lane = threadIdx.x;

    // ---- gold score (lane-strided over t) ----
    float sc = 0.f; int cnt = 0;
    for (int t = lane; t < 512; t += 32) {
        int mk = mask[b * 512 + t];
        cnt += mk;
        if (t >= 1 && mk) {
            int tp = tags[b * 512 + t - 1];
            int tc = tags[b * 512 + t];
            sc += trans[tp * 9 + tc] + g_emis[(size_t)t * 576 + b * 9 + tc];
        }
    }
    #pragma unroll
    for (int o = 16; o > 0; o >>= 1) {
        sc  += __shfl_down_sync(0xffffffffu, sc, o);
        cnt += __shfl_down_sync(0xffffffffu, cnt, o);
    }
    int len = __shfl_sync(0xffffffffu, cnt, 0);
    float score = 0.f;
    if (lane == 0) {
        int t0 = tags[b * 512];
        score = sc + start_trans[t0] + g_emis[b * 9 + t0];
        int tl = tags[b * 512 + len - 1];
        score += end_trans[tl];
    }

    // ---- forward algorithm on lanes 0..8 ----
    float logZ = 0.f;
    if (lane < 9) {
        const int j = lane;
        float tr[9];
        #pragma unroll
        for (int i = 0; i < 9; i++) tr[i] = trans[i * 9 + j];
        float alpha = start_trans[j] + g_emis[b * 9 + j];

        float em_n = g_emis[(size_t)576 + b * 9 + j];
        int   mk_n = mask[b * 512 + 1];

        for (int t = 1; t < 512; t++) {
            if (!mk_n) break;                  // mask is a contiguous prefix
            float em = em_n;
            if (t < 511) {
                em_n = g_emis[(size_t)(t + 1) * 576 + b * 9 + j];
                mk_n = mask[b * 512 + t + 1];
            } else {
                mk_n = 0;
            }
            float v[9];
            #pragma unroll
            for (int i = 0; i < 9; i++)
                v[i] = __shfl_sync(0x1ffu, alpha, i) + tr[i];
            float mx = v[0];
            #pragma unroll
            for (int i = 1; i < 9; i++) mx = fmaxf(mx, v[i]);
            float s = 0.f;
            #pragma unroll
            for (int i = 0; i < 9; i++) s += __expf(v[i] - mx);
            alpha = mx + __logf(s) + em;
        }
        float z = alpha + end_trans[j];
        float zz[9];
        #pragma unroll
        for (int i = 0; i < 9; i++) zz[i] = __shfl_sync(0x1ffu, z, i);
        float mx = zz[0];
        #pragma unroll
        for (int i = 1; i < 9; i++) mx = fmaxf(mx, zz[i]);
        float s = 0.f;
        #pragma unroll
        for (int i = 0; i < 9; i++) s += __expf(zz[i] - mx);
        logZ = mx + __logf(s);
    }
    if (lane == 0) g_llh[b] = score - logZ;
}

// ===========================================================================
// K5: final deterministic reduction  out = -mean(llh)
// ===========================================================================
__global__ void k_final(float* __restrict__ out)
{
    __shared__ float s[64];
    const int tid = threadIdx.x;
    s[tid] = g_llh[tid];
    __syncthreads();
    if (tid == 0) {
        float acc = 0.f;
        for (int i = 0; i < 64; i++) acc += s[i];
        out[0] = -acc / 64.f;
    }
}

// ===========================================================================
extern "C" void kernel_launch(void* const* d_in, const int* in_sizes, int n_in,
                              void* d_out, int out_size)
{
    const bool dictOrder = (in_sizes[2] == 15000000);
    const int ie = dictOrder ? 2 : 3;
    const int im = dictOrder ? 16 : 2;

    const int*   sent    = (const int*)  d_in[0];
    const int*   tags    = (const int*)  d_in[1];
    const float* embed   = (const float*)d_in[ie + 0];
    const float* wih_f   = (const float*)d_in[ie + 1];
    const float* whh_f   = (const float*)d_in[ie + 2];
    const float* bih_f   = (const float*)d_in[ie + 3];
    const float* bhh_f   = (const float*)d_in[ie + 4];
    const float* wih_b   = (const float*)d_in[ie + 5];
    const float* whh_b   = (const float*)d_in[ie + 6];
    const float* bih_b   = (const float*)d_in[ie + 7];
    const float* bhh_b   = (const float*)d_in[ie + 8];
    const float* w_out   = (const float*)d_in[ie + 9];
    const float* b_out   = (const float*)d_in[ie + 10];
    const float* s_tr    = (const float*)d_in[ie + 11];
    const float* e_tr    = (const float*)d_in[ie + 12];
    const float* trans   = (const float*)d_in[ie + 13];
    const int*   mask    = (const int*)  d_in[im];
    float*       out     = (float*)d_out;

    cudaFuncSetAttribute(k_rec, cudaFuncAttributeMaxDynamicSharedMemorySize, 81920);

    dim3 g1(512, 32);
    k_inproj<<<g1, 256>>>(sent, embed, wih_f, wih_b, bih_f, bhh_f, bih_b, bhh_b);
    k_rec<<<128, 256, 81920>>>(whh_f, whh_b);
    k_emis<<<512, 256>>>(w_out, b_out);
    k_crf<<<64, 32>>>(tags, mask, s_tr, e_tr, trans);
    k_final<<<1, 64>>>(out);
}

// round 5
// speedup vs baseline: 1.2015x; 1.0586x over previous
#include <cuda_runtime.h>
#include <math.h>
#include <stdint.h>

// ---------------- device scratch ----------------
__device__ float g_xp[(size_t)2 * 512 * 1024 * 64];   // [dir][t][gate_row 0..1023][b]
__device__ float g_hT[(size_t)512 * 512 * 64];        // [t][col 0..511][b]; col<256 fwd
__device__ float g_emis[(size_t)512 * 64 * 9];        // [t][b][tau]
__device__ float g_llh[64];
__device__ int g_cnt[64];                             // per-dir barrier counters (idx d*32)
__device__ int g_sense[64];                           // per-dir barrier sense

// ---------------- packed f32x2 helpers (Blackwell FFMA2) ----------------
__device__ __forceinline__ unsigned long long ffma2(unsigned long long a,
                                                    unsigned long long b,
                                                    unsigned long long c) {
    unsigned long long d;
    asm("fma.rn.f32x2 %0, %1, %2, %3;" : "=l"(d) : "l"(a), "l"(b), "l"(c));
    return d;
}
__device__ __forceinline__ unsigned long long pack2(float lo, float hi) {
    unsigned long long d;
    asm("mov.b64 %0, {%1, %2};" : "=l"(d) : "f"(lo), "f"(hi));
    return d;
}
__device__ __forceinline__ float hsum2(unsigned long long v) {
    float lo, hi;
    asm("mov.b64 {%0, %1}, %2;" : "=f"(lo), "=f"(hi) : "l"(v));
    return lo + hi;
}

// ===========================================================================
// K1: fused embedding gather + input projection GEMM (+ bih+bhh bias)
//   grid (t=512, ctile=32); 64(c) x 64(b) tile, K=300 in 5 chunks of 60.
//   Vectorized float4 smem fill (no divisions), k-pair FFMA2 compute.
// ===========================================================================
__global__ void __launch_bounds__(256) k_inproj(
    const int*   __restrict__ sent,
    const float* __restrict__ embed,
    const float* __restrict__ wih_f, const float* __restrict__ wih_b,
    const float* __restrict__ bih_f, const float* __restrict__ bhh_f,
    const float* __restrict__ bih_b, const float* __restrict__ bhh_b)
{
    __shared__ float As[64 * 68];   // wih tile [c][k], stride 68 (f4-aligned, 2-way banks)
    __shared__ float Bs[64 * 68];   // embed tile [b][k]
    __shared__ int   words[64];

    const int t     = blockIdx.x;
    const int ctile = blockIdx.y;
    const int d     = ctile >> 4;
    const int c0    = (ctile & 15) * 64;
    const int tid   = threadIdx.x;

    const float* __restrict__ wih = d ? wih_b : wih_f;
    const float* __restrict__ bih = d ? bih_b : bih_f;
    const float* __restrict__ bhh = d ? bhh_b : bhh_f;

    if (tid < 64) words[tid] = sent[tid * 512 + t];
    __syncthreads();

    const int ty = tid >> 4;   // 0..15
    const int tx = tid & 15;   // 0..15
    const int fr = tid >> 2;   // fill row 0..63
    const int fq = tid & 3;    // fill f4 group

    unsigned long long acc[4][4];
    #pragma unroll
    for (int i = 0; i < 4; i++)
        #pragma unroll
        for (int j = 0; j < 4; j++) acc[i][j] = 0ull;

    const size_t wrow = (size_t)(c0 + fr) * 300;
    const size_t erow = (size_t)words[fr] * 300;

    for (int k0 = 0; k0 < 300; k0 += 60) {
        const float* __restrict__ wsrc = wih + wrow + k0;
        const float* __restrict__ esrc = embed + erow + k0;
        #pragma unroll
        for (int u = 0; u < 4; u++) {
            int q = fq + 4 * u;
            if (q < 15) {
                *(float4*)&As[fr * 68 + q * 4] = *(const float4*)&wsrc[q * 4];
                *(float4*)&Bs[fr * 68 + q * 4] = *(const float4*)&esrc[q * 4];
            }
        }
        __syncthreads();
        #pragma unroll 6
        for (int kk = 0; kk < 30; kk++) {
            const int k = 2 * kk;
            unsigned long long a2[4], b2[4];
            #pragma unroll
            for (int i = 0; i < 4; i++)
                a2[i] = *(const unsigned long long*)&As[(ty + 16 * i) * 68 + k];
            #pragma unroll
            for (int j = 0; j < 4; j++)
                b2[j] = *(const unsigned long long*)&Bs[(tx + 16 * j) * 68 + k];
            #pragma unroll
            for (int i = 0; i < 4; i++)
                #pragma unroll
                for (int j = 0; j < 4; j++)
                    acc[i][j] = ffma2(a2[i], b2[j], acc[i][j]);
        }
        __syncthreads();
    }

    const size_t obase = ((size_t)d * 512 + t) * 65536;  // 1024*64
    #pragma unroll
    for (int i = 0; i < 4; i++) {
        int c = c0 + ty + 16 * i;
        float bias = bih[c] + bhh[c];
        #pragma unroll
        for (int j = 0; j < 4; j++)
            g_xp[obase + (size_t)c * 64 + tx + 16 * j] = hsum2(acc[i][j]) + bias;
    }
}

// ===========================================================================
// K2: persistent bidirectional LSTM recurrence.
//   grid 128 (64 CTAs/dir), 256 thr. CTA m owns h-cols [4m, 4m+4).
//   Per step: cp.async h_prev staging in 4x16KB groups overlapped with
//   chunked GEMM; register prefetch of next step's x gates; release/acquire
//   L2 sense-reversal barrier (no threadfence, no nanosleep).
//   Dynamic smem: wint 16KB + hstage 64KB = 80KB.
// ===========================================================================
__global__ void __launch_bounds__(256, 1) k_rec(
    const float* __restrict__ whh_f, const float* __restrict__ whh_b)
{
    extern __shared__ float dsm[];
    float* wint   = dsm;            // 4096 floats
    float* hstage = dsm + 4096;     // 16384 floats: [j][b]

    const int bx  = blockIdx.x;
    const int d   = bx >> 6;
    const int m   = bx & 63;
    const int hc0 = m * 4;
    const int tid = threadIdx.x;
    const int hcl = tid >> 6;       // 0..3
    const int b   = tid & 63;
    const int colbase = d * 256;
    const float* __restrict__ whh = d ? whh_b : whh_f;

    // interleaved gate-pair weight layout: [hcl][jp][ wi0,wi1,wf0,wf1,wg0,wg1,wo0,wo1 ]
    for (int idx = tid; idx < 4096; idx += 256) {
        int r  = idx >> 3, s = idx & 7;
        int hl = r >> 7,  jp = r & 127;
        int g  = s >> 1,  kb = s & 1;
        wint[idx] = whh[(size_t)(g * 256 + hc0 + hl) * 256 + 2 * jp + kb];
    }
    __syncthreads();

    const ulonglong2* __restrict__ wp = (const ulonglong2*)(wint + hcl * 1024);
    const unsigned hstage_s = (unsigned)__cvta_generic_to_shared(hstage);

    float cstate = 0.f;

    // initial x prefetch (t=0)
    {
        const int tt0 = d ? 511 : 0;
        const size_t xnb = ((size_t)d * 512 + tt0) * 65536;
        (void)xnb;
    }
    const int tt_first = d ? 511 : 0;
    size_t xb = ((size_t)d * 512 + tt_first) * 65536;
    float xi = g_xp[xb + (size_t)(hc0 + hcl) * 64 + b];
    float xf = g_xp[xb + (size_t)(256 + hc0 + hcl) * 64 + b];
    float xg = g_xp[xb + (size_t)(512 + hc0 + hcl) * 64 + b];
    float xo = g_xp[xb + (size_t)(768 + hc0 + hcl) * 64 + b];

    for (int t = 0; t < 512; t++) {
        const int tt = d ? (511 - t) : t;

        float ai, af, ag, ao;

        if (t > 0) {
            const int hp = d ? (tt + 1) : (tt - 1);
            const float4* __restrict__ srcF4 =
                (const float4*)&g_hT[(size_t)hp * 32768 + (size_t)colbase * 64];

            // issue all 4 staging groups (16 x 16B per thread total)
            #pragma unroll
            for (int q = 0; q < 4; q++) {
                #pragma unroll
                for (int r = 0; r < 4; r++) {
                    int f4i = q * 1024 + r * 256 + tid;
                    unsigned sa = hstage_s + (unsigned)f4i * 16u;
                    asm volatile("cp.async.cg.shared.global [%0], [%1], 16;"
                                 :: "r"(sa), "l"(srcF4 + f4i) : "memory");
                }
                asm volatile("cp.async.commit_group;" ::: "memory");
            }

            unsigned long long ai2 = 0, af2 = 0, ag2 = 0, ao2 = 0;

            #define GEMM_CHUNK(Q, W)                                            \
                asm volatile("cp.async.wait_group %0;" :: "n"(W) : "memory");   \
                __syncthreads();                                                \
                _Pragma("unroll 8")                                             \
                for (int jp = (Q) * 32; jp < (Q) * 32 + 32; jp++) {             \
                    float h0 = hstage[jp * 128 + b];                            \
                    float h1 = hstage[jp * 128 + 64 + b];                       \
                    unsigned long long hh = pack2(h0, h1);                      \
                    ulonglong2 w01 = wp[2 * jp];                                \
                    ulonglong2 w23 = wp[2 * jp + 1];                            \
                    ai2 = ffma2(w01.x, hh, ai2);                                \
                    af2 = ffma2(w01.y, hh, af2);                                \
                    ag2 = ffma2(w23.x, hh, ag2);                                \
                    ao2 = ffma2(w23.y, hh, ao2);                                \
                }
            GEMM_CHUNK(0, 3)
            GEMM_CHUNK(1, 2)
            GEMM_CHUNK(2, 1)
            GEMM_CHUNK(3, 0)
            #undef GEMM_CHUNK

            ai = hsum2(ai2) + xi; af = hsum2(af2) + xf;
            ag = hsum2(ag2) + xg; ao = hsum2(ao2) + xo;
        } else {
            ai = xi; af = xf; ag = xg; ao = xo;
        }

        const float si = 1.f / (1.f + __expf(-ai));
        const float sf = 1.f / (1.f + __expf(-af));
        const float so = 1.f / (1.f + __expf(-ao));
        cstate = sf * cstate + si * tanhf(ag);
        const float hval = so * tanhf(cstate);

        g_hT[(size_t)tt * 32768 + (size_t)(colbase + hc0 + hcl) * 64 + b] = hval;

        // prefetch next step's x gates (hidden under the barrier + staging)
        if (t < 511) {
            const int tn = d ? (510 - t) : (t + 1);
            const size_t xnb = ((size_t)d * 512 + tn) * 65536;
            xi = g_xp[xnb + (size_t)(hc0 + hcl) * 64 + b];
            xf = g_xp[xnb + (size_t)(256 + hc0 + hcl) * 64 + b];
            xg = g_xp[xnb + (size_t)(512 + hc0 + hcl) * 64 + b];
            xo = g_xp[xnb + (size_t)(768 + hc0 + hcl) * 64 + b];
        }

        // inter-CTA barrier (per direction): release/acquire, no L1 flush
        __syncthreads();
        if (tid == 0) {
            const int idx = d * 32;
            const int phase = (t & 1) ^ 1;
            int ticket;
            asm volatile("atom.acq_rel.gpu.global.add.s32 %0, [%1], 1;"
                         : "=r"(ticket) : "l"(&g_cnt[idx]) : "memory");
            if (ticket == 63) {
                asm volatile("st.relaxed.gpu.global.s32 [%0], 0;"
                             :: "l"(&g_cnt[idx]) : "memory");
                asm volatile("st.release.gpu.global.s32 [%0], %1;"
                             :: "l"(&g_sense[idx]), "r"(phase) : "memory");
            } else {
                int s;
                do {
                    asm volatile("ld.acquire.gpu.global.s32 %0, [%1];"
                                 : "=r"(s) : "l"(&g_sense[idx]) : "memory");
                } while (s != phase);
            }
        }
        __syncthreads();
    }
}

// ===========================================================================
// K3: emissions GEMM  emis[t][b][tau] = sum_c hT[t][c][b]*w_out[tau][c]+b_out
// ===========================================================================
__global__ void __launch_bounds__(256) k_emis(
    const float* __restrict__ w_out, const float* __restrict__ b_out)
{
    __shared__ float w_s[9 * 512];
    __shared__ float red[4][64][10];

    const int t = blockIdx.x, tid = threadIdx.x;
    for (int i = tid; i < 9 * 512; i += 256) w_s[i] = w_out[i];
    __syncthreads();

    const int b = tid & 63, seg = tid >> 6;
    float acc[9] = {};
    const float* hbase = &g_hT[(size_t)t * 32768];
    const int cbeg = seg * 128;
    for (int c = cbeg; c < cbeg + 128; c++) {
        float hv = hbase[(size_t)c * 64 + b];
        #pragma unroll
        for (int tau = 0; tau < 9; tau++) acc[tau] += hv * w_s[tau * 512 + c];
    }
    #pragma unroll
    for (int tau = 0; tau < 9; tau++) red[seg][b][tau] = acc[tau];
    __syncthreads();
    if (seg == 0) {
        #pragma unroll
        for (int tau = 0; tau < 9; tau++) {
            float v = red[0][b][tau] + red[1][b][tau] + red[2][b][tau] +
                      red[3][b][tau] + b_out[tau];
            g_emis[(size_t)t * 576 + b * 9 + tau] = v;
        }
    }
}

// ===========================================================================
// K4: CRF gold score + forward algorithm (logZ). grid 64 (b), 1 warp each.
//     Normalized linear-space recurrence with precomputed exp(trans):
//     2 MUFU per step instead of ~10, no max tree.
// ===========================================================================
__global__ void k_crf(
    const int*   __restrict__ tags, const int* __restrict__ mask,
    const float* __restrict__ start_trans, const float* __restrict__ end_trans,
    const float* __restrict__ trans)
{
    const int b = blockIdx.x, lane = threadIdx.x;

    // ---- gold score (lane-strided over t) ----
    float sc = 0.f; int cnt = 0;
    for (int t = lane; t < 512; t += 32) {
        int mk = mask[b * 512 + t];
        cnt += mk;
        if (t >= 1 && mk) {
            int tp = tags[b * 512 + t - 1];
            int tc = tags[b * 512 + t];
            sc += trans[tp * 9 + tc] + g_emis[(size_t)t * 576 + b * 9 + tc];
        }
    }
    #pragma unroll
    for (int o = 16; o > 0; o >>= 1) {
        sc  += __shfl_down_sync(0xffffffffu, sc, o);
        cnt += __shfl_down_sync(0xffffffffu, cnt, o);
    }
    int len = __shfl_sync(0xffffffffu, cnt, 0);
    float score = 0.f;
    if (lane == 0) {
        int t0 = tags[b * 512];
        score = sc + start_trans[t0] + g_emis[b * 9 + t0];
        int tl = tags[b * 512 + len - 1];
        score += end_trans[tl];
    }

    // ---- forward algorithm on lanes 0..8 (normalized linear space) ----
    float logZ = 0.f;
    if (lane < 9) {
        const int j = lane;
        float E[9];
        #pragma unroll
        for (int i = 0; i < 9; i++) E[i] = __expf(trans[i * 9 + j]);

        float a = start_trans[j] + g_emis[b * 9 + j];
        float a0 = __shfl_sync(0x1ffu, a, 0);
        float base = a0;
        a -= a0;

        float em_n = g_emis[(size_t)576 + b * 9 + j];
        int   mk_n = mask[b * 512 + 1];

        for (int t = 1; t < 512; t++) {
            if (!mk_n) break;                  // mask is a contiguous prefix
            float em = em_n;
            if (t < 511) {
                em_n = g_emis[(size_t)(t + 1) * 576 + b * 9 + j];
                mk_n = mask[b * 512 + t + 1];
            } else {
                mk_n = 0;
            }
            float ea = __expf(a);
            float s0 = 0.f, s1 = 0.f, s2 = 0.f;
            #pragma unroll
            for (int i = 0; i < 9; i += 3) {
                float e0 = __shfl_sync(0x1ffu, ea, i);
                float e1 = __shfl_sync(0x1ffu, ea, i + 1);
                float e2 = __shfl_sync(0x1ffu, ea, i + 2);
                s0 += e0 * E[i];
                s1 += e1 * E[i + 1];
                s2 += e2 * E[i + 2];
            }
            float u = __logf(s0 + s1 + s2) + em;
            float u0 = __shfl_sync(0x1ffu, u, 0);
            base += u0;
            a = u - u0;
        }
        float z = a + end_trans[j];
        float ez = __expf(z);
        float s = 0.f;
        #pragma unroll
        for (int i = 0; i < 9; i++) s += __shfl_sync(0x1ffu, ez, i);
        logZ = base + __logf(s);
    }
    if (lane == 0) g_llh[b] = score - logZ;
}

// ===========================================================================
// K5: final deterministic reduction  out = -mean(llh)
// ===========================================================================
__global__ void k_final(float* __restrict__ out)
{
    __shared__ float s[64];
    const int tid = threadIdx.x;
    s[tid] = g_llh[tid];
    __syncthreads();
    if (tid == 0) {
        float acc = 0.f;
        for (int i = 0; i < 64; i++) acc += s[i];
        out[0] = -acc / 64.f;
    }
}

// ===========================================================================
extern "C" void kernel_launch(void* const* d_in, const int* in_sizes, int n_in,
                              void* d_out, int out_size)
{
    const bool dictOrder = (in_sizes[2] == 15000000);
    const int ie = dictOrder ? 2 : 3;
    const int im = dictOrder ? 16 : 2;

    const int*   sent    = (const int*)  d_in[0];
    const int*   tags    = (const int*)  d_in[1];
    const float* embed   = (const float*)d_in[ie + 0];
    const float* wih_f   = (const float*)d_in[ie + 1];
    const float* whh_f   = (const float*)d_in[ie + 2];
    const float* bih_f   = (const float*)d_in[ie + 3];
    const float* bhh_f   = (const float*)d_in[ie + 4];
    const float* wih_b   = (const float*)d_in[ie + 5];
    const float* whh_b   = (const float*)d_in[ie + 6];
    const float* bih_b   = (const float*)d_in[ie + 7];
    const float* bhh_b   = (const float*)d_in[ie + 8];
    const float* w_out   = (const float*)d_in[ie + 9];
    const float* b_out   = (const float*)d_in[ie + 10];
    const float* s_tr    = (const float*)d_in[ie + 11];
    const float* e_tr    = (const float*)d_in[ie + 12];
    const float* trans   = (const float*)d_in[ie + 13];
    const int*   mask    = (const int*)  d_in[im];
    float*       out     = (float*)d_out;

    cudaFuncSetAttribute(k_rec, cudaFuncAttributeMaxDynamicSharedMemorySize, 81920);

    dim3 g1(512, 32);
    k_inproj<<<g1, 256>>>(sent, embed, wih_f, wih_b, bih_f, bhh_f, bih_b, bhh_b);
    k_rec<<<128, 256, 81920>>>(whh_f, whh_b);
    k_emis<<<512, 256>>>(w_out, b_out);
    k_crf<<<64, 32>>>(tags, mask, s_tr, e_tr, trans);
    k_final<<<1, 64>>>(out);
}

// round 6
// speedup vs baseline: 1.3028x; 1.0843x over previous
#include <cuda_runtime.h>
#include <math.h>
#include <stdint.h>

// ---------------- device scratch ----------------
__device__ float g_xp[(size_t)2 * 512 * 1024 * 64];   // [dir][t][gate_row 0..1023][b]
__device__ float g_hP[(size_t)512 * 2 * 64 * 64 * 4]; // [t][d][jq][b][4]  (64MB)
__device__ float g_emis[(size_t)512 * 64 * 9];        // [t][b][tau]
__device__ float g_llh[64];
__device__ int   g_cnt[1024];                         // sub-counters: [d*512 + sub*32]

// ---------------- packed f32x2 helpers (Blackwell FFMA2) ----------------
__device__ __forceinline__ unsigned long long ffma2(unsigned long long a,
                                                    unsigned long long b,
                                                    unsigned long long c) {
    unsigned long long d;
    asm("fma.rn.f32x2 %0, %1, %2, %3;" : "=l"(d) : "l"(a), "l"(b), "l"(c));
    return d;
}
__device__ __forceinline__ float hsum2(unsigned long long v) {
    float lo, hi;
    asm("mov.b64 {%0, %1}, %2;" : "=f"(lo), "=f"(hi) : "l"(v));
    return lo + hi;
}
__device__ __forceinline__ float tanh_ap(float x) {
    float y;
    asm("tanh.approx.f32 %0, %1;" : "=f"(y) : "f"(x));
    return y;
}
__device__ __forceinline__ float sig_ap(float x) {
    return 0.5f * tanh_ap(0.5f * x) + 0.5f;
}

// ===========================================================================
// K1: fused embedding gather + input projection GEMM (+ bih+bhh bias)
// ===========================================================================
__global__ void __launch_bounds__(256) k_inproj(
    const int*   __restrict__ sent,
    const float* __restrict__ embed,
    const float* __restrict__ wih_f, const float* __restrict__ wih_b,
    const float* __restrict__ bih_f, const float* __restrict__ bhh_f,
    const float* __restrict__ bih_b, const float* __restrict__ bhh_b)
{
    __shared__ float As[64 * 68];
    __shared__ float Bs[64 * 68];
    __shared__ int   words[64];

    const int t     = blockIdx.x;
    const int ctile = blockIdx.y;
    const int d     = ctile >> 4;
    const int c0    = (ctile & 15) * 64;
    const int tid   = threadIdx.x;

    const float* __restrict__ wih = d ? wih_b : wih_f;
    const float* __restrict__ bih = d ? bih_b : bih_f;
    const float* __restrict__ bhh = d ? bhh_b : bhh_f;

    if (tid < 64) words[tid] = sent[tid * 512 + t];
    __syncthreads();

    const int ty = tid >> 4;
    const int tx = tid & 15;
    const int fr = tid >> 2;
    const int fq = tid & 3;

    unsigned long long acc[4][4];
    #pragma unroll
    for (int i = 0; i < 4; i++)
        #pragma unroll
        for (int j = 0; j < 4; j++) acc[i][j] = 0ull;

    const size_t wrow = (size_t)(c0 + fr) * 300;
    const size_t erow = (size_t)words[fr] * 300;

    for (int k0 = 0; k0 < 300; k0 += 60) {
        const float* __restrict__ wsrc = wih + wrow + k0;
        const float* __restrict__ esrc = embed + erow + k0;
        #pragma unroll
        for (int u = 0; u < 4; u++) {
            int q = fq + 4 * u;
            if (q < 15) {
                *(float4*)&As[fr * 68 + q * 4] = *(const float4*)&wsrc[q * 4];
                *(float4*)&Bs[fr * 68 + q * 4] = *(const float4*)&esrc[q * 4];
            }
        }
        __syncthreads();
        #pragma unroll 6
        for (int kk = 0; kk < 30; kk++) {
            const int k = 2 * kk;
            unsigned long long a2[4], b2[4];
            #pragma unroll
            for (int i = 0; i < 4; i++)
                a2[i] = *(const unsigned long long*)&As[(ty + 16 * i) * 68 + k];
            #pragma unroll
            for (int j = 0; j < 4; j++)
                b2[j] = *(const unsigned long long*)&Bs[(tx + 16 * j) * 68 + k];
            #pragma unroll
            for (int i = 0; i < 4; i++)
                #pragma unroll
                for (int j = 0; j < 4; j++)
                    acc[i][j] = ffma2(a2[i], b2[j], acc[i][j]);
        }
        __syncthreads();
    }

    const size_t obase = ((size_t)d * 512 + t) * 65536;
    #pragma unroll
    for (int i = 0; i < 4; i++) {
        int c = c0 + ty + 16 * i;
        float bias = bih[c] + bhh[c];
        #pragma unroll
        for (int j = 0; j < 4; j++)
            g_xp[obase + (size_t)c * 64 + tx + 16 * j] = hsum2(acc[i][j]) + bias;
    }
}

// ===========================================================================
// K2: persistent bidirectional LSTM recurrence.
//   128 CTAs (64/dir), 256 thr; CTA m owns cols [4m,4m+4); thread=(hcl,b).
//   h in quad-interleaved g_hP; per jq: 1 LDS.128 h + 4 broadcast LDS.128 w
//   + 8 FFMA2. Monotone 8-sub-counter barrier (red.release arrivals, relaxed
//   sum-poll + fence.acq_rel); counters reset by k_emis next in stream.
// ===========================================================================
__global__ void __launch_bounds__(256, 1) k_rec(
    const float* __restrict__ whh_f, const float* __restrict__ whh_b)
{
    extern __shared__ float dsm[];
    float* wint   = dsm;            // 4096 floats (16KB): f4[(hcl*4+g)*64+jq]
    float* hstage = dsm + 4096;     // 16384 floats (64KB): f4[jq*64+b]

    const int bx  = blockIdx.x;
    const int d   = bx >> 6;
    const int m   = bx & 63;
    const int hc0 = m * 4;
    const int tid = threadIdx.x;
    const int hcl = tid >> 6;       // 0..3 : local column
    const int b   = tid & 63;
    const float* __restrict__ whh = d ? whh_b : whh_f;

    // weight quads: wint f4 row (hcl*4+g), col jq  -> whh[(g*256+hc0+hcl)][4jq..]
    for (int q = tid; q < 1024; q += 256) {
        int row = q >> 6, jq = q & 63;
        int g = row & 3, hl = row >> 2;
        *(float4*)&wint[q * 4] =
            *(const float4*)&whh[(size_t)(g * 256 + hc0 + hl) * 256 + 4 * jq];
    }
    __syncthreads();

    const ulonglong2* __restrict__ w2 = (const ulonglong2*)wint;
    const float4* __restrict__ hst4 = (const float4*)hstage;
    const unsigned hstage_s = (unsigned)__cvta_generic_to_shared(hstage);
    const int wr0 = (hcl * 4 + 0) * 64;
    const int wr1 = (hcl * 4 + 1) * 64;
    const int wr2 = (hcl * 4 + 2) * 64;
    const int wr3 = (hcl * 4 + 3) * 64;

    int* __restrict__ cbase = &g_cnt[d * 512];

    float cstate = 0.f;

    const int tt_first = d ? 511 : 0;
    size_t xb = ((size_t)d * 512 + tt_first) * 65536;
    float xi = g_xp[xb + (size_t)(hc0 + hcl) * 64 + b];
    float xf = g_xp[xb + (size_t)(256 + hc0 + hcl) * 64 + b];
    float xg = g_xp[xb + (size_t)(512 + hc0 + hcl) * 64 + b];
    float xo = g_xp[xb + (size_t)(768 + hc0 + hcl) * 64 + b];

    for (int t = 0; t < 512; t++) {
        const int tt = d ? (511 - t) : t;

        float ai, af, ag, ao;

        if (t > 0) {
            // wait for all 64 CTAs of this direction to finish step t-1
            if (tid == 0) {
                const int target = 64 * t;
                int s;
                do {
                    s = 0;
                    #pragma unroll
                    for (int i = 0; i < 8; i++) {
                        int v;
                        asm volatile("ld.relaxed.gpu.global.s32 %0, [%1];"
                                     : "=r"(v) : "l"(cbase + i * 32));
                        s += v;
                    }
                } while (s < target);
                asm volatile("fence.acq_rel.gpu;" ::: "memory");
            }
            __syncthreads();

            const int hp = d ? (tt + 1) : (tt - 1);
            const float4* __restrict__ srcF4 =
                (const float4*)&g_hP[((size_t)hp * 2 + d) * 16384];

            #pragma unroll
            for (int q = 0; q < 4; q++) {
                #pragma unroll
                for (int r = 0; r < 4; r++) {
                    int f4i = q * 1024 + r * 256 + tid;
                    unsigned sa = hstage_s + (unsigned)f4i * 16u;
                    asm volatile("cp.async.cg.shared.global [%0], [%1], 16;"
                                 :: "r"(sa), "l"(srcF4 + f4i) : "memory");
                }
                asm volatile("cp.async.commit_group;" ::: "memory");
            }

            unsigned long long a0 = 0, a1 = 0, a2 = 0, a3 = 0;

            #define GEMM_CHUNK(Q, W)                                            \
                asm volatile("cp.async.wait_group %0;" :: "n"(W) : "memory");   \
                __syncthreads();                                                \
                _Pragma("unroll")                                               \
                for (int jq = (Q) * 16; jq < (Q) * 16 + 16; jq++) {             \
                    ulonglong2 h2 = *(const ulonglong2*)&hst4[jq * 64 + b];     \
                    ulonglong2 q0 = w2[wr0 + jq];                               \
                    ulonglong2 q1 = w2[wr1 + jq];                               \
                    ulonglong2 q2 = w2[wr2 + jq];                               \
                    ulonglong2 q3 = w2[wr3 + jq];                               \
                    a0 = ffma2(q0.x, h2.x, a0); a0 = ffma2(q0.y, h2.y, a0);     \
                    a1 = ffma2(q1.x, h2.x, a1); a1 = ffma2(q1.y, h2.y, a1);     \
                    a2 = ffma2(q2.x, h2.x, a2); a2 = ffma2(q2.y, h2.y, a2);     \
                    a3 = ffma2(q3.x, h2.x, a3); a3 = ffma2(q3.y, h2.y, a3);     \
                }
            GEMM_CHUNK(0, 3)
            GEMM_CHUNK(1, 2)
            GEMM_CHUNK(2, 1)
            GEMM_CHUNK(3, 0)
            #undef GEMM_CHUNK

            ai = hsum2(a0) + xi; af = hsum2(a1) + xf;
            ag = hsum2(a2) + xg; ao = hsum2(a3) + xo;
        } else {
            ai = xi; af = xf; ag = xg; ao = xo;
        }

        const float si = sig_ap(ai);
        const float sf = sig_ap(af);
        const float so = sig_ap(ao);
        cstate = sf * cstate + si * tanh_ap(ag);
        const float hval = so * tanh_ap(cstate);

        // quad-interleaved store: [tt][d][jq=m][b][k=hcl]
        g_hP[((size_t)tt * 2 + d) * 16384 + (size_t)(m * 64 + b) * 4 + hcl] = hval;

        // prefetch next step's x gates
        if (t < 511) {
            const int tn = d ? (510 - t) : (t + 1);
            const size_t xnb = ((size_t)d * 512 + tn) * 65536;
            xi = g_xp[xnb + (size_t)(hc0 + hcl) * 64 + b];
            xf = g_xp[xnb + (size_t)(256 + hc0 + hcl) * 64 + b];
            xg = g_xp[xnb + (size_t)(512 + hc0 + hcl) * 64 + b];
            xo = g_xp[xnb + (size_t)(768 + hc0 + hcl) * 64 + b];
        }

        // arrival: fire-and-forget release add on this CTA's sub-counter
        __syncthreads();
        if (tid == 0) {
            asm volatile("red.release.gpu.global.add.s32 [%0], 1;"
                         :: "l"(cbase + (m & 7) * 32) : "memory");
        }
    }
}

// ===========================================================================
// K3: emissions from g_hP + barrier-counter reset for next graph replay.
//   emis[t][b][tau] = sum_{d,jq,k} hP[t][d][jq][b][k]*w_out[tau][d*256+4jq+k]
// ===========================================================================
__global__ void __launch_bounds__(256) k_emis(
    const float* __restrict__ w_out, const float* __restrict__ b_out)
{
    if (blockIdx.x == 0 && threadIdx.x < 16)
        g_cnt[(threadIdx.x >> 3) * 512 + (threadIdx.x & 7) * 32] = 0;

    __shared__ float w_s[9 * 512];
    __shared__ float red[4][64][10];

    const int t = blockIdx.x, tid = threadIdx.x;
    for (int i = tid; i < 9 * 512; i += 256) w_s[i] = w_out[i];
    __syncthreads();

    const int b = tid & 63, seg = tid >> 6;
    const int d = seg >> 1, jq0 = (seg & 1) * 32;
    float acc[9] = {};
    const float4* __restrict__ hp4 =
        (const float4*)&g_hP[((size_t)t * 2 + d) * 16384];
    for (int jq = jq0; jq < jq0 + 32; jq++) {
        float4 h4 = hp4[jq * 64 + b];
        const int cb = d * 256 + 4 * jq;
        #pragma unroll
        for (int tau = 0; tau < 9; tau++) {
            acc[tau] += h4.x * w_s[tau * 512 + cb + 0]
                      + h4.y * w_s[tau * 512 + cb + 1]
                      + h4.z * w_s[tau * 512 + cb + 2]
                      + h4.w * w_s[tau * 512 + cb + 3];
        }
    }
    #pragma unroll
    for (int tau = 0; tau < 9; tau++) red[seg][b][tau] = acc[tau];
    __syncthreads();
    if (seg == 0) {
        #pragma unroll
        for (int tau = 0; tau < 9; tau++) {
            float v = red[0][b][tau] + red[1][b][tau] + red[2][b][tau] +
                      red[3][b][tau] + b_out[tau];
            g_emis[(size_t)t * 576 + b * 9 + tau] = v;
        }
    }
}

// ===========================================================================
// K4: CRF gold score + forward algorithm (logZ). grid 64 (b), 1 warp each.
// ===========================================================================
__global__ void k_crf(
    const int*   __restrict__ tags, const int* __restrict__ mask,
    const float* __restrict__ start_trans, const float* __restrict__ end_trans,
    const float* __restrict__ trans)
{
    const int b = blockIdx.x, lane = threadIdx.x;

    float sc = 0.f; int cnt = 0;
    for (int t = lane; t < 512; t += 32) {
        int mk = mask[b * 512 + t];
        cnt += mk;
        if (t >= 1 && mk) {
            int tp = tags[b * 512 + t - 1];
            int tc = tags[b * 512 + t];
            sc += trans[tp * 9 + tc] + g_emis[(size_t)t * 576 + b * 9 + tc];
        }
    }
    #pragma unroll
    for (int o = 16; o > 0; o >>= 1) {
        sc  += __shfl_down_sync(0xffffffffu, sc, o);
        cnt += __shfl_down_sync(0xffffffffu, cnt, o);
    }
    int len = __shfl_sync(0xffffffffu, cnt, 0);
    float score = 0.f;
    if (lane == 0) {
        int t0 = tags[b * 512];
        score = sc + start_trans[t0] + g_emis[b * 9 + t0];
        int tl = tags[b * 512 + len - 1];
        score += end_trans[tl];
    }

    float logZ = 0.f;
    if (lane < 9) {
        const int j = lane;
        float E[9];
        #pragma unroll
        for (int i = 0; i < 9; i++) E[i] = __expf(trans[i * 9 + j]);

        float a = start_trans[j] + g_emis[b * 9 + j];
        float a0 = __shfl_sync(0x1ffu, a, 0);
        float base = a0;
        a -= a0;

        float em_n = g_emis[(size_t)576 + b * 9 + j];
        int   mk_n = mask[b * 512 + 1];

        for (int t = 1; t < 512; t++) {
            if (!mk_n) break;
            float em = em_n;
            if (t < 511) {
                em_n = g_emis[(size_t)(t + 1) * 576 + b * 9 + j];
                mk_n = mask[b * 512 + t + 1];
            } else {
                mk_n = 0;
            }
            float ea = __expf(a);
            float s0 = 0.f, s1 = 0.f, s2 = 0.f;
            #pragma unroll
            for (int i = 0; i < 9; i += 3) {
                float e0 = __shfl_sync(0x1ffu, ea, i);
                float e1 = __shfl_sync(0x1ffu, ea, i + 1);
                float e2 = __shfl_sync(0x1ffu, ea, i + 2);
                s0 += e0 * E[i];
                s1 += e1 * E[i + 1];
                s2 += e2 * E[i + 2];
            }
            float u = __logf(s0 + s1 + s2) + em;
            float u0 = __shfl_sync(0x1ffu, u, 0);
            base += u0;
            a = u - u0;
        }
        float z = a + end_trans[j];
        float ez = __expf(z);
        float s = 0.f;
        #pragma unroll
        for (int i = 0; i < 9; i++) s += __shfl_sync(0x1ffu, ez, i);
        logZ = base + __logf(s);
    }
    if (lane == 0) g_llh[b] = score - logZ;
}

// ===========================================================================
// K5: final deterministic reduction  out = -mean(llh)
// ===========================================================================
__global__ void k_final(float* __restrict__ out)
{
    __shared__ float s[64];
    const int tid = threadIdx.x;
    s[tid] = g_llh[tid];
    __syncthreads();
    if (tid == 0) {
        float acc = 0.f;
        for (int i = 0; i < 64; i++) acc += s[i];
        out[0] = -acc / 64.f;
    }
}

// ===========================================================================
extern "C" void kernel_launch(void* const* d_in, const int* in_sizes, int n_in,
                              void* d_out, int out_size)
{
    const bool dictOrder = (in_sizes[2] == 15000000);
    const int ie = dictOrder ? 2 : 3;
    const int im = dictOrder ? 16 : 2;

    const int*   sent    = (const int*)  d_in[0];
    const int*   tags    = (const int*)  d_in[1];
    const float* embed   = (const float*)d_in[ie + 0];
    const float* wih_f   = (const float*)d_in[ie + 1];
    const float* whh_f   = (const float*)d_in[ie + 2];
    const float* bih_f   = (const float*)d_in[ie + 3];
    const float* bhh_f   = (const float*)d_in[ie + 4];
    const float* wih_b   = (const float*)d_in[ie + 5];
    const float* whh_b   = (const float*)d_in[ie + 6];
    const float* bih_b   = (const float*)d_in[ie + 7];
    const float* bhh_b   = (const float*)d_in[ie + 8];
    const float* w_out   = (const float*)d_in[ie + 9];
    const float* b_out   = (const float*)d_in[ie + 10];
    const float* s_tr    = (const float*)d_in[ie + 11];
    const float* e_tr    = (const float*)d_in[ie + 12];
    const float* trans   = (const float*)d_in[ie + 13];
    const int*   mask    = (const int*)  d_in[im];
    float*       out     = (float*)d_out;

    cudaFuncSetAttribute(k_rec, cudaFuncAttributeMaxDynamicSharedMemorySize, 81920);

    dim3 g1(512, 32);
    k_inproj<<<g1, 256>>>(sent, embed, wih_f, wih_b, bih_f, bhh_f, bih_b, bhh_b);
    k_rec<<<128, 256, 81920>>>(whh_f, whh_b);
    k_emis<<<512, 256>>>(w_out, b_out);
    k_crf<<<64, 32>>>(tags, mask, s_tr, e_tr, trans);
    k_final<<<1, 64>>>(out);
}